// round 3
// baseline (speedup 1.0000x reference)
#include <cuda_runtime.h>
#include <cuda_bf16.h>
#include <cstdint>

#define NUM_HEADS   8
#define HIDDEN_DIM  64
#define N_REAL      30000
#define N_VIRT      2000
#define N_NODES     (N_REAL + N_VIRT)
#define N_EDGES     512000
#define VEC_PER_ROW (HIDDEN_DIM / 4)   // 16 float4 per node row

// Scratch (device globals; allocation-free per harness rules)
__device__ float4 g_h0[N_NODES * VEC_PER_ROW];   // node features, 8 MB
__device__ float4 g_h1[N_NODES * VEC_PER_ROW];   // round-1 accumulator, 8 MB
__device__ float4 g_h2[N_VIRT * VEC_PER_ROW];    // round-2 accumulator (virtual only), 512 KB
__device__ int    g_indeg[N_NODES];
__device__ float  g_winv[N_NODES];               // 1 / indeg

__device__ __forceinline__ void red_add_v4(float4* addr, float4 v) {
    asm volatile("red.global.add.v4.f32 [%0], {%1,%2,%3,%4};"
                 :: "l"(addr), "f"(v.x), "f"(v.y), "f"(v.z), "f"(v.w)
                 : "memory");
}

// ---------------------------------------------------------------------------
// K1: in-degree histogram
__global__ void k_indeg(const int* __restrict__ dst) {
    int e = blockIdx.x * blockDim.x + threadIdx.x;
    if (e >= N_EDGES) return;
    atomicAdd(&g_indeg[dst[e]], 1);
}

// K1b: reciprocal degree (per node, once)
__global__ void k_winv() {
    int v = blockIdx.x * blockDim.x + threadIdx.x;
    if (v >= N_NODES) return;
    int d = g_indeg[v];
    g_winv[v] = d > 0 ? (1.0f / (float)d) : 0.0f;
}

// K2: build h0 = concat(features[cnodes], virtue_emb)
__global__ void k_build_h0(const float4* __restrict__ features,
                           const float4* __restrict__ virtue_emb,
                           const int* __restrict__ cnodes) {
    int t = blockIdx.x * blockDim.x + threadIdx.x;
    if (t >= N_NODES * VEC_PER_ROW) return;
    int v = t >> 4;
    int c = t & 15;
    float4 x;
    if (v < N_REAL) {
        int w = cnodes[v];
        x = features[(size_t)w * VEC_PER_ROW + c];
    } else {
        x = virtue_emb[(size_t)(v - N_REAL) * VEC_PER_ROW + c];
    }
    g_h0[t] = x;
}

// K3: round 1 — h1[dst] += h0[src] * winv[dst], all edges. 16 threads/edge.
__global__ void k_round1(const int* __restrict__ src,
                         const int* __restrict__ dst) {
    int t = blockIdx.x * blockDim.x + threadIdx.x;
    if (t >= N_EDGES * VEC_PER_ROW) return;
    int e = t >> 4;
    int c = t & 15;
    int s = src[e];
    int d = dst[e];
    float w = g_winv[d];
    float4 x = g_h0[s * VEC_PER_ROW + c];
    x.x *= w; x.y *= w; x.z *= w; x.w *= w;
    red_add_v4(&g_h1[d * VEC_PER_ROW + c], x);
}

// K4: round 2 — only virtual destinations matter for the output.
__global__ void k_round2(const int* __restrict__ src,
                         const int* __restrict__ dst) {
    int t = blockIdx.x * blockDim.x + threadIdx.x;
    if (t >= N_EDGES * VEC_PER_ROW) return;
    int e = t >> 4;
    int d = dst[e];
    if (d < N_REAL) return;             // ~94% of warps exit here together
    int c = t & 15;
    int s = src[e];
    float w = g_winv[d];
    float4 x = g_h1[s * VEC_PER_ROW + c];
    x.x *= w; x.y *= w; x.z *= w; x.w *= w;
    red_add_v4(&g_h2[(d - N_REAL) * VEC_PER_ROW + c], x);
}

// K5: broadcast h2 across the 8 (identical) heads into the output.
__global__ void k_write_out(const int* __restrict__ vm_idx,
                            float4* __restrict__ out) {
    int t = blockIdx.x * blockDim.x + threadIdx.x;
    if (t >= N_VIRT * VEC_PER_ROW) return;
    int v = t >> 4;
    int c = t & 15;
    int u = vm_idx[v] - N_REAL;
    float4 x = g_h2[u * VEC_PER_ROW + c];
#pragma unroll
    for (int h = 0; h < NUM_HEADS; h++) {
        out[((size_t)v * NUM_HEADS + h) * VEC_PER_ROW + c] = x;
    }
}

// ---------------------------------------------------------------------------
extern "C" void kernel_launch(void* const* d_in, const int* in_sizes, int n_in,
                              void* d_out, int out_size) {
    const float4* features   = (const float4*)d_in[0];  // [100000,64] f32
    const float4* virtue_emb = (const float4*)d_in[1];  // [2000,64]   f32
    const int*    cnodes     = (const int*)d_in[2];     // [30000] i32
    const int*    src        = (const int*)d_in[3];     // [512000] i32
    const int*    dst        = (const int*)d_in[4];     // [512000] i32
    const int*    vm_idx     = (const int*)d_in[5];     // [2000] i32
    float4*       out        = (float4*)d_out;          // [2000,8,64] f32

    void *p_h1, *p_h2, *p_indeg;
    cudaGetSymbolAddress(&p_h1, g_h1);
    cudaGetSymbolAddress(&p_h2, g_h2);
    cudaGetSymbolAddress(&p_indeg, g_indeg);

    cudaMemsetAsync(p_h1, 0, sizeof(float4) * N_NODES * VEC_PER_ROW, 0);
    cudaMemsetAsync(p_h2, 0, sizeof(float4) * N_VIRT * VEC_PER_ROW, 0);
    cudaMemsetAsync(p_indeg, 0, sizeof(int) * N_NODES, 0);

    const int TB = 256;
    k_indeg    <<<(N_EDGES + TB - 1) / TB, TB>>>(dst);
    k_winv     <<<(N_NODES + TB - 1) / TB, TB>>>();
    k_build_h0 <<<(N_NODES * VEC_PER_ROW + TB - 1) / TB, TB>>>(features, virtue_emb, cnodes);
    k_round1   <<<(N_EDGES * VEC_PER_ROW + TB - 1) / TB, TB>>>(src, dst);
    k_round2   <<<(N_EDGES * VEC_PER_ROW + TB - 1) / TB, TB>>>(src, dst);
    k_write_out<<<(N_VIRT * VEC_PER_ROW + TB - 1) / TB, TB>>>(vm_idx, out);
}